// round 1
// baseline (speedup 1.0000x reference)
#include <cuda_runtime.h>
#include <cstdint>

// Problem constants
#define BB 4
#define SS 1024
#define DD 1024
#define HH 16
#define HD 64
#define MROWS (BB*SS)          // 4096
#define QSCALE 0.03125f        // 1024^-0.5

// Scratch (static device allocations are allowed; cudaMalloc is not)
__device__ float g_qkv[(size_t)MROWS * 3 * DD];              // 50.3 MB  [4096, 3072]
__device__ float g_p[(size_t)BB * HH * SS * SS];             // 268 MB   [b,h,q,k]
__device__ float g_ao[(size_t)MROWS * DD];                   // 16.8 MB  [4096, 1024]

// ---------------------------------------------------------------------------
// Tiled SGEMM: C[M,N] = A[M,K] @ B[K,N] + bias[N], cols < scale_cols get *scale
// BM=BN=128, BK=16, 256 threads, 8x8 per thread
// ---------------------------------------------------------------------------
__global__ __launch_bounds__(256) void sgemm_bias(
    const float* __restrict__ A, const float* __restrict__ B,
    const float* __restrict__ bias, float* __restrict__ C,
    int M, int N, int K, int scale_cols, float scale)
{
    const int BM = 128, BN = 128, BK = 16;
    __shared__ float As[BK][BM];
    __shared__ float Bs[BK][BN];

    int bx = blockIdx.x;            // N direction
    int by = blockIdx.y;            // M direction
    int tid = threadIdx.x;
    int tx = tid & 15;              // 0..15 -> col groups of 8
    int ty = tid >> 4;              // 0..15 -> row groups of 8

    int arow  = tid >> 2;           // 0..63 (x2 passes for 128 rows)
    int acol4 = tid & 3;            // float4 index along K (BK=16 -> 4)
    int brow  = tid >> 5;           // 0..7 (x2 passes for 16 rows)
    int bcol4 = tid & 31;           // float4 index along N (128/4=32)

    float acc[8][8];
    #pragma unroll
    for (int i = 0; i < 8; i++)
        #pragma unroll
        for (int j = 0; j < 8; j++) acc[i][j] = 0.f;

    for (int kt = 0; kt < K; kt += BK) {
        #pragma unroll
        for (int r = 0; r < 2; r++) {
            int row = arow + r * 64;
            float4 a = *(const float4*)&A[(size_t)(by * BM + row) * K + kt + acol4 * 4];
            As[acol4 * 4 + 0][row] = a.x;
            As[acol4 * 4 + 1][row] = a.y;
            As[acol4 * 4 + 2][row] = a.z;
            As[acol4 * 4 + 3][row] = a.w;
        }
        #pragma unroll
        for (int r = 0; r < 2; r++) {
            int row = brow + r * 8;
            float4 bv = *(const float4*)&B[(size_t)(kt + row) * N + bx * BN + bcol4 * 4];
            *(float4*)&Bs[row][bcol4 * 4] = bv;
        }
        __syncthreads();

        #pragma unroll
        for (int kk = 0; kk < BK; kk++) {
            float am[8], bn[8];
            float4 a0 = *(float4*)&As[kk][ty * 8];
            float4 a1 = *(float4*)&As[kk][ty * 8 + 4];
            am[0]=a0.x; am[1]=a0.y; am[2]=a0.z; am[3]=a0.w;
            am[4]=a1.x; am[5]=a1.y; am[6]=a1.z; am[7]=a1.w;
            float4 b0 = *(float4*)&Bs[kk][tx * 8];
            float4 b1 = *(float4*)&Bs[kk][tx * 8 + 4];
            bn[0]=b0.x; bn[1]=b0.y; bn[2]=b0.z; bn[3]=b0.w;
            bn[4]=b1.x; bn[5]=b1.y; bn[6]=b1.z; bn[7]=b1.w;
            #pragma unroll
            for (int i = 0; i < 8; i++)
                #pragma unroll
                for (int j = 0; j < 8; j++)
                    acc[i][j] += am[i] * bn[j];
        }
        __syncthreads();
    }

    int rowC = by * BM + ty * 8;
    int colC = bx * BN + tx * 8;
    #pragma unroll
    for (int i = 0; i < 8; i++) {
        #pragma unroll
        for (int j = 0; j < 8; j++) {
            int col = colC + j;
            float v = acc[i][j] + bias[col];
            if (col < scale_cols) v *= scale;
            C[(size_t)(rowC + i) * N + col] = v;
        }
    }
}

// ---------------------------------------------------------------------------
// Fused scores + softmax per (b, h, 32-q-row tile).
// Keeps the whole 32x1024 score tile in shared memory, does warp softmax,
// writes probabilities to g_p.
// Dynamic smem: Ssc[32*1024] + Qs[64*33] + Ks[64*129]  = 172,544 bytes
// ---------------------------------------------------------------------------
#define QT 32
#define SC_SMEM ((QT*SS + 64*(QT+1) + 64*129) * sizeof(float))

__global__ __launch_bounds__(256) void attn_scores_softmax(
    const float* __restrict__ qkv, float* __restrict__ P)
{
    extern __shared__ float sm[];
    float* Ssc = sm;                       // [QT][1024]
    float* Qs  = Ssc + QT * SS;            // [64][QT+1]  d-major
    float* Ks  = Qs + 64 * (QT + 1);       // [64][129]   d-major, 128 keys/iter

    int b  = blockIdx.z;
    int h  = blockIdx.y;
    int q0 = blockIdx.x * QT;
    int tid = threadIdx.x;

    // Load Q tile (already scaled in QKV epilogue): Qs[d][q]
    for (int i = tid; i < QT * 64; i += 256) {
        int q = i >> 6, d = i & 63;
        Qs[d * (QT + 1) + q] = qkv[(size_t)(b * SS + q0 + q) * (3 * DD) + h * HD + d];
    }

    // Loop over key tiles of 128
    for (int kt = 0; kt < SS; kt += 128) {
        __syncthreads();
        for (int i = tid; i < 128 * 64; i += 256) {
            int k = i >> 6, d = i & 63;
            Ks[d * 129 + k] = qkv[(size_t)(b * SS + kt + k) * (3 * DD) + DD + h * HD + d];
        }
        __syncthreads();

        int tx = tid & 31;     // key lane
        int ty = tid >> 5;     // q group (0..7), 4 rows each
        float acc[4][4];
        #pragma unroll
        for (int i = 0; i < 4; i++)
            #pragma unroll
            for (int j = 0; j < 4; j++) acc[i][j] = 0.f;

        #pragma unroll 8
        for (int d = 0; d < 64; d++) {
            float kv[4];
            #pragma unroll
            for (int j = 0; j < 4; j++) kv[j] = Ks[d * 129 + tx + j * 32];
            #pragma unroll
            for (int i = 0; i < 4; i++) {
                float qv = Qs[d * (QT + 1) + ty * 4 + i];
                #pragma unroll
                for (int j = 0; j < 4; j++) acc[i][j] += qv * kv[j];
            }
        }
        #pragma unroll
        for (int i = 0; i < 4; i++)
            #pragma unroll
            for (int j = 0; j < 4; j++)
                Ssc[(ty * 4 + i) * SS + kt + tx + j * 32] = acc[i][j];
    }
    __syncthreads();

    // Softmax: each warp handles 4 rows
    int lane = tid & 31, w = tid >> 5;
    for (int r = w * 4; r < w * 4 + 4; r++) {
        const float* row = Ssc + r * SS;
        float v[32];
        float m = -1e30f;
        #pragma unroll
        for (int i = 0; i < 32; i++) {
            v[i] = row[lane + i * 32];
            m = fmaxf(m, v[i]);
        }
        #pragma unroll
        for (int o = 16; o; o >>= 1) m = fmaxf(m, __shfl_xor_sync(0xffffffffu, m, o));
        float s = 0.f;
        #pragma unroll
        for (int i = 0; i < 32; i++) { v[i] = __expf(v[i] - m); s += v[i]; }
        #pragma unroll
        for (int o = 16; o; o >>= 1) s += __shfl_xor_sync(0xffffffffu, s, o);
        float inv = 1.f / s;
        size_t base = ((size_t)(b * HH + h) * SS + q0 + r) * SS;
        #pragma unroll
        for (int i = 0; i < 32; i++) P[base + lane + i * 32] = v[i] * inv;
    }
}

// ---------------------------------------------------------------------------
// PV GEMM: out_head[b,q,h,d] = sum_k P[b,h,q,k] * V[b,k,h,d]
// Per (b,h,64-q tile). 256 threads, 4x4 per thread.
// ---------------------------------------------------------------------------
__global__ __launch_bounds__(256) void attn_pv(
    const float* __restrict__ P, const float* __restrict__ qkv,
    float* __restrict__ AO)
{
    __shared__ float Ps[64][65];
    __shared__ float Vs[64][64];

    int b  = blockIdx.z;
    int h  = blockIdx.y;
    int q0 = blockIdx.x * 64;
    int tid = threadIdx.x;
    int tx = tid & 15;      // d quarter (d = tx + j*16)
    int ty = tid >> 4;      // q group (q = ty*4 + i)

    float acc[4][4];
    #pragma unroll
    for (int i = 0; i < 4; i++)
        #pragma unroll
        for (int j = 0; j < 4; j++) acc[i][j] = 0.f;

    for (int kt = 0; kt < SS; kt += 64) {
        __syncthreads();
        for (int i = tid; i < 64 * 64; i += 256) {
            int r = i >> 6, c = i & 63;
            Ps[r][c] = P[((size_t)(b * HH + h) * SS + q0 + r) * SS + kt + c];
            Vs[r][c] = qkv[(size_t)(b * SS + kt + r) * (3 * DD) + 2 * DD + h * HD + c];
        }
        __syncthreads();

        #pragma unroll 8
        for (int k = 0; k < 64; k++) {
            float bb[4], aa[4];
            #pragma unroll
            for (int j = 0; j < 4; j++) bb[j] = Vs[k][tx + j * 16];
            #pragma unroll
            for (int i = 0; i < 4; i++) aa[i] = Ps[ty * 4 + i][k];
            #pragma unroll
            for (int i = 0; i < 4; i++)
                #pragma unroll
                for (int j = 0; j < 4; j++) acc[i][j] += aa[i] * bb[j];
        }
    }

    #pragma unroll
    for (int i = 0; i < 4; i++)
        #pragma unroll
        for (int j = 0; j < 4; j++)
            AO[(size_t)(b * SS + q0 + ty * 4 + i) * DD + h * HD + tx + j * 16] = acc[i][j];
}

// ---------------------------------------------------------------------------
// attn_mean[b,q,k] = (1/H) * sum_h P[b,h,q,k]
// ---------------------------------------------------------------------------
__global__ __launch_bounds__(256) void attn_mean_kernel(
    const float* __restrict__ P, float* __restrict__ outm)
{
    size_t idx = (size_t)blockIdx.x * 256 + threadIdx.x;   // B*S*S total
    int k = (int)(idx & 1023);
    size_t t = idx >> 10;
    int q = (int)(t & 1023);
    int b = (int)(t >> 10);
    float s = 0.f;
    #pragma unroll
    for (int h = 0; h < HH; h++)
        s += P[((size_t)(b * HH + h) * SS + q) * SS + k];
    outm[idx] = s * (1.0f / HH);
}

// ---------------------------------------------------------------------------
// Host launcher
// ---------------------------------------------------------------------------
extern "C" void kernel_launch(void* const* d_in, const int* in_sizes, int n_in,
                              void* d_out, int out_size)
{
    const float* x     = (const float*)d_in[0];   // [4,1024,1024]
    const float* w_in  = (const float*)d_in[1];   // [1024,3072]
    const float* b_in  = (const float*)d_in[2];   // [3072]
    const float* w_out = (const float*)d_in[3];   // [1024,1024]
    const float* b_out = (const float*)d_in[4];   // [1024]
    float* out = (float*)d_out;                   // [0:4194304) out, [4194304:) attn_mean

    float *qkv, *P, *AO;
    cudaGetSymbolAddress((void**)&qkv, g_qkv);
    cudaGetSymbolAddress((void**)&P,   g_p);
    cudaGetSymbolAddress((void**)&AO,  g_ao);

    cudaFuncSetAttribute(attn_scores_softmax,
                         cudaFuncAttributeMaxDynamicSharedMemorySize, (int)SC_SMEM);

    // 1. QKV GEMM with fused q-scaling
    sgemm_bias<<<dim3(3 * DD / 128, MROWS / 128), 256>>>(
        x, w_in, b_in, qkv, MROWS, 3 * DD, DD, DD, QSCALE);

    // 2. scores + softmax -> P
    attn_scores_softmax<<<dim3(SS / QT, HH, BB), 256, SC_SMEM>>>(qkv, P);

    // 3. P @ V -> AO
    attn_pv<<<dim3(SS / 64, HH, BB), 256>>>(P, qkv, AO);

    // 4. head-mean -> second half of d_out
    attn_mean_kernel<<<(BB * SS * SS) / 256, 256>>>(P, out + (size_t)BB * SS * SS);

    // 5. output projection -> first half of d_out
    sgemm_bias<<<dim3(DD / 128, MROWS / 128), 256>>>(
        AO, w_out, b_out, out, MROWS, DD, DD, 0, 1.0f);
}

// round 2
// speedup vs baseline: 1.4577x; 1.4577x over previous
#include <cuda_runtime.h>
#include <cstdint>

// Problem constants
#define BB 4
#define SS 1024
#define DD 1024
#define HH 16
#define HD 64
#define MROWS (BB*SS)          // 4096
#define QSCALE 0.03125f        // 1024^-0.5

typedef unsigned long long u64;

// Scratch
__device__ float g_qkv[(size_t)MROWS * 3 * DD];              // [4096, 3072]
__device__ float g_p[(size_t)BB * HH * SS * SS];             // [b,h,q,k]
__device__ float g_ao[(size_t)MROWS * DD];                   // [4096, 1024]

// ---------------------------------------------------------------------------
// f32x2 packed-FMA helpers (Blackwell)
// ---------------------------------------------------------------------------
__device__ __forceinline__ void fma2(u64& d, u64 a, u64 b) {
    asm("fma.rn.f32x2 %0, %1, %2, %0;" : "+l"(d) : "l"(a), "l"(b));
}
__device__ __forceinline__ u64 pack2(float x, float y) {
    u64 r; asm("mov.b64 %0, {%1, %2};" : "=l"(r) : "f"(x), "f"(y)); return r;
}
__device__ __forceinline__ u64 dup2(float x) { return pack2(x, x); }
__device__ __forceinline__ float2 unpk(u64 v) {
    float2 r; asm("mov.b64 {%0, %1}, %2;" : "=f"(r.x), "=f"(r.y) : "l"(v)); return r;
}

// ---------------------------------------------------------------------------
// SGEMM with f32x2: C[M,N] = A[M,K] @ B[K,N] + bias; cols < scale_cols get *scale
// BM=BN=128, BK=16, 256 threads. Per thread: 16 rows (warp-uniform) x 4 cols.
// ---------------------------------------------------------------------------
__global__ __launch_bounds__(256) void sgemm_bias(
    const float* __restrict__ A, const float* __restrict__ B,
    const float* __restrict__ bias, float* __restrict__ C,
    int M, int N, int K, int scale_cols, float scale)
{
    const int BM = 128, BN = 128, BK = 16;
    __shared__ float As[BK][BM];   // [k][m]
    __shared__ float Bs[BK][BN];   // [k][n]

    int bx = blockIdx.x, by = blockIdx.y;
    int tid  = threadIdx.x;
    int lane = tid & 31;           // 4 cols: lane*4
    int wrp  = tid >> 5;           // 16 rows: wrp*16

    int arow  = tid >> 2;          // 0..63 (x2)
    int acol4 = tid & 3;
    int brow  = tid >> 5;          // 0..7 (x2)
    int bcol4 = tid & 31;

    u64 acc[8][4];
    #pragma unroll
    for (int i = 0; i < 8; i++)
        #pragma unroll
        for (int j = 0; j < 4; j++) acc[i][j] = 0ull;

    for (int kt = 0; kt < K; kt += BK) {
        #pragma unroll
        for (int r = 0; r < 2; r++) {
            int row = arow + r * 64;
            float4 a = *(const float4*)&A[(size_t)(by * BM + row) * K + kt + acol4 * 4];
            As[acol4 * 4 + 0][row] = a.x;
            As[acol4 * 4 + 1][row] = a.y;
            As[acol4 * 4 + 2][row] = a.z;
            As[acol4 * 4 + 3][row] = a.w;
        }
        #pragma unroll
        for (int r = 0; r < 2; r++) {
            int row = brow + r * 8;
            *(float4*)&Bs[row][bcol4 * 4] =
                *(const float4*)&B[(size_t)(kt + row) * N + bx * BN + bcol4 * 4];
        }
        __syncthreads();

        #pragma unroll
        for (int kk = 0; kk < BK; kk++) {
            // 8 row-pairs, warp-uniform address (broadcast)
            ulonglong2 a0 = *(const ulonglong2*)&As[kk][wrp * 16 + 0];
            ulonglong2 a1 = *(const ulonglong2*)&As[kk][wrp * 16 + 4];
            ulonglong2 a2 = *(const ulonglong2*)&As[kk][wrp * 16 + 8];
            ulonglong2 a3 = *(const ulonglong2*)&As[kk][wrp * 16 + 12];
            u64 am[8] = {a0.x, a0.y, a1.x, a1.y, a2.x, a2.y, a3.x, a3.y};
            float4 b = *(const float4*)&Bs[kk][lane * 4];
            u64 bd[4] = {dup2(b.x), dup2(b.y), dup2(b.z), dup2(b.w)};
            #pragma unroll
            for (int i = 0; i < 8; i++)
                #pragma unroll
                for (int j = 0; j < 4; j++)
                    fma2(acc[i][j], am[i], bd[j]);
        }
        __syncthreads();
    }

    int col0 = bx * BN + lane * 4;
    float4 bv = *(const float4*)&bias[col0];
    bool sc = (col0 < scale_cols);   // uniform per block (boundaries multiple of 128)
    #pragma unroll
    for (int rp = 0; rp < 8; rp++) {
        float2 c0 = unpk(acc[rp][0]), c1 = unpk(acc[rp][1]);
        float2 c2 = unpk(acc[rp][2]), c3 = unpk(acc[rp][3]);
        float4 lo = make_float4(c0.x + bv.x, c1.x + bv.y, c2.x + bv.z, c3.x + bv.w);
        float4 hi = make_float4(c0.y + bv.x, c1.y + bv.y, c2.y + bv.z, c3.y + bv.w);
        if (sc) {
            lo.x *= scale; lo.y *= scale; lo.z *= scale; lo.w *= scale;
            hi.x *= scale; hi.y *= scale; hi.z *= scale; hi.w *= scale;
        }
        int row = by * BM + wrp * 16 + rp * 2;
        *(float4*)&C[(size_t)row * N + col0]       = lo;
        *(float4*)&C[(size_t)(row + 1) * N + col0] = hi;
    }
}

// ---------------------------------------------------------------------------
// Fused scores + softmax per (b, h, 32-q tile). f32x2 inner product.
// Ks tile [64 d][256 k] with XOR swizzle on k bits 2..4 by (d>>2)&7.
// Dyn smem: Ssc[32*1024] + Qs[64*36] + Ks[64*256] = 205,824 B
// ---------------------------------------------------------------------------
#define QT 32
#define KT2 256
#define SC_SMEM ((QT*SS + 64*36 + 64*KT2) * sizeof(float))

__global__ __launch_bounds__(256) void attn_scores_softmax(
    const float* __restrict__ qkv, float* __restrict__ P)
{
    extern __shared__ float sm[];
    float* Ssc = sm;                       // [QT][1024]
    float* Qs  = Ssc + QT * SS;            // [64][36] d-major (rows of q)
    float* Ks  = Qs + 64 * 36;             // [64][256] d-major, swizzled

    int b  = blockIdx.z;
    int h  = blockIdx.y;
    int q0 = blockIdx.x * QT;
    int tid = threadIdx.x;
    int lane = tid & 31;
    int wq   = tid >> 5;                   // 4 q rows: wq*4

    // Q tile (already scaled): Qs[d][q]
    for (int i = tid; i < QT * 64; i += 256) {
        int q = i >> 6, d = i & 63;
        Qs[d * 36 + q] = qkv[(size_t)(b * SS + q0 + q) * (3 * DD) + h * HD + d];
    }

    for (int kt = 0; kt < SS; kt += KT2) {
        __syncthreads();
        // Fill Ks (transpose with swizzle)
        #pragma unroll
        for (int it = 0; it < 16; it++) {
            int i = tid + it * 256;
            int k = i >> 4, d4 = i & 15;
            float4 v = *(const float4*)&qkv[(size_t)(b * SS + kt + k) * (3 * DD) + DD + h * HD + d4 * 4];
            int sw = (d4 & 7) << 2;        // (d>>2)&7 for d = d4*4+c
            Ks[(d4 * 4 + 0) * KT2 + (k ^ sw)] = v.x;
            Ks[(d4 * 4 + 1) * KT2 + (k ^ sw)] = v.y;
            Ks[(d4 * 4 + 2) * KT2 + (k ^ sw)] = v.z;
            Ks[(d4 * 4 + 3) * KT2 + (k ^ sw)] = v.w;
        }
        __syncthreads();

        u64 acc[2][8];
        #pragma unroll
        for (int i = 0; i < 2; i++)
            #pragma unroll
            for (int j = 0; j < 8; j++) acc[i][j] = 0ull;

        #pragma unroll 4
        for (int d = 0; d < 64; d++) {
            ulonglong2 a = *(const ulonglong2*)&Qs[d * 36 + wq * 4];   // broadcast
            int sw = ((d >> 2) & 7) << 2;
            int kb = (lane * 4) ^ sw;
            float4 b0 = *(const float4*)&Ks[d * KT2 + kb];
            float4 b1 = *(const float4*)&Ks[d * KT2 + 128 + kb];
            u64 bd[8] = {dup2(b0.x), dup2(b0.y), dup2(b0.z), dup2(b0.w),
                         dup2(b1.x), dup2(b1.y), dup2(b1.z), dup2(b1.w)};
            #pragma unroll
            for (int j = 0; j < 8; j++) {
                fma2(acc[0][j], a.x, bd[j]);
                fma2(acc[1][j], a.y, bd[j]);
            }
        }

        // Store score tile (unswizzled)
        #pragma unroll
        for (int rp = 0; rp < 2; rp++) {
            float2 c0 = unpk(acc[rp][0]), c1 = unpk(acc[rp][1]);
            float2 c2 = unpk(acc[rp][2]), c3 = unpk(acc[rp][3]);
            float2 c4 = unpk(acc[rp][4]), c5 = unpk(acc[rp][5]);
            float2 c6 = unpk(acc[rp][6]), c7 = unpk(acc[rp][7]);
            int rlo = wq * 4 + rp * 2, rhi = rlo + 1;
            *(float4*)&Ssc[rlo * SS + kt + lane * 4]       = make_float4(c0.x, c1.x, c2.x, c3.x);
            *(float4*)&Ssc[rlo * SS + kt + 128 + lane * 4] = make_float4(c4.x, c5.x, c6.x, c7.x);
            *(float4*)&Ssc[rhi * SS + kt + lane * 4]       = make_float4(c0.y, c1.y, c2.y, c3.y);
            *(float4*)&Ssc[rhi * SS + kt + 128 + lane * 4] = make_float4(c4.y, c5.y, c6.y, c7.y);
        }
    }
    __syncthreads();

    // Softmax: each warp handles 4 rows
    for (int r = wq * 4; r < wq * 4 + 4; r++) {
        const float* row = Ssc + r * SS;
        float v[32];
        float m = -1e30f;
        #pragma unroll
        for (int i = 0; i < 32; i++) {
            v[i] = row[lane + i * 32];
            m = fmaxf(m, v[i]);
        }
        #pragma unroll
        for (int o = 16; o; o >>= 1) m = fmaxf(m, __shfl_xor_sync(0xffffffffu, m, o));
        float s = 0.f;
        #pragma unroll
        for (int i = 0; i < 32; i++) { v[i] = __expf(v[i] - m); s += v[i]; }
        #pragma unroll
        for (int o = 16; o; o >>= 1) s += __shfl_xor_sync(0xffffffffu, s, o);
        float inv = 1.f / s;
        size_t base = ((size_t)(b * HH + h) * SS + q0 + r) * SS;
        #pragma unroll
        for (int i = 0; i < 32; i++) P[base + lane + i * 32] = v[i] * inv;
    }
}

// ---------------------------------------------------------------------------
// PV GEMM: AO[b,q,h,d] = sum_k P[b,h,q,k] * V[b,k,h,d]
// Block: 128 q x 64 d. Ps stored transposed [k][q] so q-pairs are native u64.
// ---------------------------------------------------------------------------
__global__ __launch_bounds__(256) void attn_pv(
    const float* __restrict__ P, const float* __restrict__ qkv,
    float* __restrict__ AO)
{
    __shared__ float Ps[64 * 132];   // [k][128 q + pad4]
    __shared__ float Vs[64 * 68];    // [k][64 d + pad4]

    int b  = blockIdx.z;
    int h  = blockIdx.y;
    int q0 = blockIdx.x * 128;
    int tid = threadIdx.x;
    int tx = tid & 15;      // d cols: tx*4
    int ty = tid >> 4;      // q rows: ty*8 .. +7

    u64 acc[4][4];          // [q-pair][d col]
    #pragma unroll
    for (int i = 0; i < 4; i++)
        #pragma unroll
        for (int j = 0; j < 4; j++) acc[i][j] = 0ull;

    for (int kt = 0; kt < SS; kt += 64) {
        __syncthreads();
        // Ps fill: transpose P rows (coalesced along k)
        #pragma unroll
        for (int it = 0; it < 8; it++) {
            int i = tid + it * 256;
            int q = i >> 4, k4 = i & 15;
            float4 pv = *(const float4*)&P[((size_t)(b * HH + h) * SS + q0 + q) * SS + kt + k4 * 4];
            Ps[(k4 * 4 + 0) * 132 + q] = pv.x;
            Ps[(k4 * 4 + 1) * 132 + q] = pv.y;
            Ps[(k4 * 4 + 2) * 132 + q] = pv.z;
            Ps[(k4 * 4 + 3) * 132 + q] = pv.w;
        }
        // Vs fill
        #pragma unroll
        for (int it = 0; it < 4; it++) {
            int i = tid + it * 256;
            int k = i >> 4, d4 = i & 15;
            *(float4*)&Vs[k * 68 + d4 * 4] =
                *(const float4*)&qkv[(size_t)(b * SS + kt + k) * (3 * DD) + 2 * DD + h * HD + d4 * 4];
        }
        __syncthreads();

        #pragma unroll 4
        for (int k = 0; k < 64; k++) {
            ulonglong2 p0 = *(const ulonglong2*)&Ps[k * 132 + ty * 8];
            ulonglong2 p1 = *(const ulonglong2*)&Ps[k * 132 + ty * 8 + 4];
            u64 am[4] = {p0.x, p0.y, p1.x, p1.y};
            float4 v = *(const float4*)&Vs[k * 68 + tx * 4];
            u64 vd[4] = {dup2(v.x), dup2(v.y), dup2(v.z), dup2(v.w)};
            #pragma unroll
            for (int i = 0; i < 4; i++)
                #pragma unroll
                for (int j = 0; j < 4; j++)
                    fma2(acc[i][j], am[i], vd[j]);
        }
    }

    #pragma unroll
    for (int qp = 0; qp < 4; qp++) {
        float2 c0 = unpk(acc[qp][0]), c1 = unpk(acc[qp][1]);
        float2 c2 = unpk(acc[qp][2]), c3 = unpk(acc[qp][3]);
        int qlo = q0 + ty * 8 + qp * 2;
        *(float4*)&AO[(size_t)(b * SS + qlo) * DD + h * HD + tx * 4] =
            make_float4(c0.x, c1.x, c2.x, c3.x);
        *(float4*)&AO[(size_t)(b * SS + qlo + 1) * DD + h * HD + tx * 4] =
            make_float4(c0.y, c1.y, c2.y, c3.y);
    }
}

// ---------------------------------------------------------------------------
// attn_mean[b,q,k] = (1/H) * sum_h P[b,h,q,k]   (DRAM-bound, 83% of peak)
// ---------------------------------------------------------------------------
__global__ __launch_bounds__(256) void attn_mean_kernel(
    const float* __restrict__ P, float* __restrict__ outm)
{
    size_t idx = (size_t)blockIdx.x * 256 + threadIdx.x;
    int k = (int)(idx & 1023);
    size_t t = idx >> 10;
    int q = (int)(t & 1023);
    int b = (int)(t >> 10);
    float s = 0.f;
    #pragma unroll
    for (int h = 0; h < HH; h++)
        s += P[((size_t)(b * HH + h) * SS + q) * SS + k];
    outm[idx] = s * (1.0f / HH);
}

// ---------------------------------------------------------------------------
// Host launcher
// ---------------------------------------------------------------------------
extern "C" void kernel_launch(void* const* d_in, const int* in_sizes, int n_in,
                              void* d_out, int out_size)
{
    const float* x     = (const float*)d_in[0];
    const float* w_in  = (const float*)d_in[1];
    const float* b_in  = (const float*)d_in[2];
    const float* w_out = (const float*)d_in[3];
    const float* b_out = (const float*)d_in[4];
    float* out = (float*)d_out;

    float *qkv, *P, *AO;
    cudaGetSymbolAddress((void**)&qkv, g_qkv);
    cudaGetSymbolAddress((void**)&P,   g_p);
    cudaGetSymbolAddress((void**)&AO,  g_ao);

    cudaFuncSetAttribute(attn_scores_softmax,
                         cudaFuncAttributeMaxDynamicSharedMemorySize, (int)SC_SMEM);

    // 1. QKV GEMM with fused q-scaling
    sgemm_bias<<<dim3(3 * DD / 128, MROWS / 128), 256>>>(
        x, w_in, b_in, qkv, MROWS, 3 * DD, DD, DD, QSCALE);

    // 2. scores + softmax -> P
    attn_scores_softmax<<<dim3(SS / QT, HH, BB), 256, SC_SMEM>>>(qkv, P);

    // 3. P @ V -> AO
    attn_pv<<<dim3(SS / 128, HH, BB), 256>>>(P, qkv, AO);

    // 4. head-mean
    attn_mean_kernel<<<(BB * SS * SS) / 256, 256>>>(P, out + (size_t)BB * SS * SS);

    // 5. output projection
    sgemm_bias<<<dim3(DD / 128, MROWS / 128), 256>>>(
        AO, w_out, b_out, out, MROWS, DD, DD, 0, 1.0f);
}